// round 15
// baseline (speedup 1.0000x reference)
#include <cuda_runtime.h>
#include <cuda_fp16.h>
#include <cstdint>

#define HW   256
#define OHW  512
#define XP   257          // padded spatial dim (halo row/col of zeros)
#define XP2  (XP*XP)      // 66049
#define NPIX (4 * XP2)    // 264196 pixel rows

// ---------------------------------------------------------------------------
// g_xh: [b][y][x][c] fp16, 128B per (b,y,x), zero-padded at y/x==256 (+tail).
// g_u : [b][y][x][r] fp16 (r<16), u = x . low1^T, 32B per pixel.
// g_BpH: per (py, tapidx) 64(n) x 64(c) fp16 high weights, SW128 pre-swizzled.
// g_BpL: per (py, tapidx) 64(o) x 16(r) fp16 low2 weights, 24-half row pitch.
//   tapidx j: j<nty -> px=0 (ty=j,tx=0,kx=1); else jj=j-nty: px=1,
//   ty=jj>>1, tx=jj&1, kx = tx?0:2.  ky = py ? (ty?0:2) : 1.
// ---------------------------------------------------------------------------
__device__ __align__(16) __half g_xh[(NPIX + 256) * 64];
__device__ __align__(16) __half g_u [(NPIX + 256) * 16];
__device__ __align__(16) __half g_BpH[2][6][64 * 64];
__device__ __align__(16) __half g_BpL[2][6][64 * 24];
__device__ float g_biaslow[4][64];

static __device__ __forceinline__ uint32_t swz128(uint32_t off) {
    return off ^ ((off >> 3) & 0x70);
}
static __device__ __forceinline__ uint32_t smem_u32(const void* p) {
    uint32_t a;
    asm("{ .reg .u64 t; cvta.to.shared.u64 t, %1; cvt.u32.u64 %0, t; }" : "=r"(a) : "l"(p));
    return a;
}
static __device__ __forceinline__ void ldsm4(uint32_t r[4], uint32_t a) {
    asm volatile("ldmatrix.sync.aligned.m8n8.x4.shared.b16 {%0,%1,%2,%3}, [%4];"
        : "=r"(r[0]), "=r"(r[1]), "=r"(r[2]), "=r"(r[3]) : "r"(a));
}
static __device__ __forceinline__ void mma16816(float c[4], const uint32_t a[4],
                                                uint32_t b0, uint32_t b1) {
    asm volatile(
        "mma.sync.aligned.m16n8k16.row.col.f32.f16.f16.f32 "
        "{%0,%1,%2,%3}, {%4,%5,%6,%7}, {%8,%9}, {%0,%1,%2,%3};"
        : "+f"(c[0]), "+f"(c[1]), "+f"(c[2]), "+f"(c[3])
        : "r"(a[0]), "r"(a[1]), "r"(a[2]), "r"(a[3]), "r"(b0), "r"(b1));
}
#define CP16(dst, src) \
    asm volatile("cp.async.cg.shared.global [%0], [%1], 16;" :: "r"(dst), "l"(src))
#define CP_COMMIT() asm volatile("cp.async.commit_group;" ::: "memory")
#define CP_WAIT0()  asm volatile("cp.async.wait_group 0;" ::: "memory")
#define CP_WAIT1()  asm volatile("cp.async.wait_group 1;" ::: "memory")

// ---------------------------------------------------------------------------
// Prep (fully fused): transpose x -> [b][y][x][c] fp16, u = x . low1^T -> g_u,
// weight packing on the 12 nearly-empty blocks (b==0, xc==256, y<12).
// Stage 1 uses cp.async into an xor-chunked fp32 tile (chunk q of row c lands
// at q ^ (c>>3)) -> stage-2 channel gathers are bank-conflict-FREE.
// ---------------------------------------------------------------------------
__global__ void prep_xu(const float* __restrict__ x,
                        const float* __restrict__ low1_w,
                        const float* __restrict__ high_w,
                        const float* __restrict__ low1_b,
                        const float* __restrict__ low2_w,
                        const float* __restrict__ low2_b)
{
    __shared__ __align__(16) float tile[64 * 64];   // xor-chunk swizzled
    __shared__ __align__(16) char axs[8192];        // 64 rows x 128B, row-xor
    __shared__ __align__(16) char w1s[2048];        // 16 rows x 128B, SW128
    const int y  = blockIdx.x;            // 0..256
    const int xc = blockIdx.y * 64;       // 0,64,128,192,256
    const int b  = blockIdx.z;
    const int tid = threadIdx.x;
    const int lane = tid & 31;
    const int w = tid >> 5;
    const uint32_t st = smem_u32(tile);

    // ---- fused weight packing on 12 otherwise-idle blocks ----
    if (b == 0 && blockIdx.y == 4 && y < 12) {
        const int py = y / 6, j = y % 6;
        const int nty = py ? 2 : 1;
        const int T = 3 * nty;
        if (j < T) {
            int px, ty, tx;
            if (j < nty) { px = 0; ty = j; tx = 0; }
            else { const int jj = j - nty; px = 1; ty = jj >> 1; tx = jj & 1; }
            const int ky = py ? (ty ? 0 : 2) : 1;
            const int kx = px ? (tx ? 0 : 2) : 1;
            for (int idx = tid; idx < 64 * 64; idx += 256) {
                const int n = idx >> 6, c = idx & 63;
                g_BpH[py][j][swz128((uint32_t)n * 128 + c * 2) >> 1] =
                    __float2half(high_w[((c * 64 + n) * 3 + ky) * 3 + kx]);
            }
            for (int idx = tid; idx < 64 * 16; idx += 256) {
                const int o = idx >> 4, r = idx & 15;
                g_BpL[py][j][o * 24 + r] =
                    __float2half(low2_w[((r * 64 + o) * 3 + ky) * 3 + kx]);
            }
        }
        if (j == 0 && tid < 128) {
            const int px = tid >> 6, o = tid & 63;
            const int ntx = px ? 2 : 1;
            float s = low2_b[o];
            for (int ty = 0; ty < nty; ++ty)
                for (int tx = 0; tx < ntx; ++tx) {
                    const int ky = py ? (ty ? 0 : 2) : 1;
                    const int kx = px ? (tx ? 0 : 2) : 1;
                    for (int r = 0; r < 16; ++r)
                        s += low1_b[r] * low2_w[((r * 64 + o) * 3 + ky) * 3 + kx];
                }
            g_biaslow[py * 2 + px][o] = s;
        }
    }

    if (tid < 128) {
        const float* src = low1_w + (tid >> 3) * 64 + (tid & 7) * 8;
        __half h[8];
        #pragma unroll
        for (int k = 0; k < 8; ++k) h[k] = __float2half(src[k]);
        const uint32_t off = (uint32_t)(tid >> 3) * 128 + (tid & 7) * 16;
        *(uint4*)(w1s + (off ^ (((tid >> 3) & 7) << 4))) = *(const uint4*)h;
    }

    // ---- stage 1: fp32 tile fill (cp.async, xor-chunk layout) ----
    if (y < HW && xc < HW) {
        #pragma unroll
        for (int it = 0; it < 4; ++it) {
            const int e = it * 256 + tid;      // 1024 16B chunks
            const int c = e >> 4, q = e & 15;
            const char* src = (const char*)(x + (((size_t)b * 64 + c) * HW + y) * HW + xc)
                              + q * 16;
            CP16(st + (uint32_t)c * 256 + ((uint32_t)(q ^ (c >> 3)) << 4), src);
        }
        CP_COMMIT();
        CP_WAIT0();
    } else {
        #pragma unroll
        for (int it = 0; it < 16; ++it) tile[it * 256 + tid] = 0.f;
    }
    __syncthreads();

    // ---- stage 2: fp16 convert -> axs (for GEMM) + g_xh global ----
    #pragma unroll
    for (int it = 0; it < 2; ++it) {
        const int i = it * 256 + tid;          // 512 uint4 tasks
        const int xl = i >> 3, g = i & 7, ch = g << 3;
        const int xx = xc + xl;
        const float* trow = tile + ch * 64 + (((xl >> 2) ^ g) << 2) + (xl & 3);
        __half h[8];
        #pragma unroll
        for (int k = 0; k < 8; ++k) h[k] = __float2half(trow[k * 64]);
        const uint4 val = *(const uint4*)h;
        const uint32_t aoff = (uint32_t)xl * 128 + g * 16;
        *(uint4*)(axs + (aoff ^ (((uint32_t)(xl & 7)) << 4))) = val;
        if (xx <= 256)
            *(uint4*)&g_xh[((size_t)b * XP2 + (size_t)y * XP + xx) * 64 + ch] = val;
    }
    __syncthreads();

    // ---- stage 3: u = X . W1^T (warps 0-1) ----
    if (w < 2) {
        const uint32_t sa = smem_u32(axs), sw = smem_u32(w1s);
        float acc[2][2][4];
        #pragma unroll
        for (int i = 0; i < 2; ++i)
            #pragma unroll
            for (int j = 0; j < 2; ++j)
                #pragma unroll
                for (int k = 0; k < 4; ++k) acc[i][j][k] = 0.f;

        const int brow = (lane & 7) + ((lane >> 4) << 3);
        const int bkk  = ((lane >> 3) & 1) << 4;
        #pragma unroll
        for (int ks = 0; ks < 4; ++ks) {
            uint32_t a[2][4];
            const int arow = lane & 15;
            const int akb = ks * 32 + ((lane >> 4) << 4);
            #pragma unroll
            for (int mf = 0; mf < 2; ++mf) {
                const int row = w * 32 + mf * 16 + arow;
                ldsm4(a[mf], sa + (uint32_t)row * 128
                              + ((uint32_t)akb ^ ((uint32_t)(row & 7) << 4)));
            }
            uint32_t bw[4];
            ldsm4(bw, sw + swz128((uint32_t)brow * 128 + ks * 32 + bkk));
            #pragma unroll
            for (int mf = 0; mf < 2; ++mf) {
                mma16816(acc[mf][0], a[mf], bw[0], bw[1]);
                mma16816(acc[mf][1], a[mf], bw[2], bw[3]);
            }
        }
        #pragma unroll
        for (int mf = 0; mf < 2; ++mf)
            #pragma unroll
            for (int j = 0; j < 2; ++j)
                #pragma unroll
                for (int rh = 0; rh < 2; ++rh) {
                    const int row = w * 32 + mf * 16 + (lane >> 2) + rh * 8;
                    const int xx = xc + row;
                    if (xx <= 256) {
                        const int col = j * 8 + (lane & 3) * 2;
                        __half2 hv = __floats2half2_rn(acc[mf][j][rh * 2],
                                                       acc[mf][j][rh * 2 + 1]);
                        *(__half2*)&g_u[((size_t)b * XP2 + (size_t)y * XP + xx) * 16
                                        + col] = hv;
                    }
                }
    }
}

// SMEM map (main kernel) — everything resident, read-only after one sync.
#define A_OFF      0
#define HALO_ROWS  153                 // 9 x 17
#define U_OFF      19584               // 153 x 48B
#define BH_OFF     27008               // 6 x 8192
#define BL_OFF     (BH_OFF + 6 * 8192) // 76160; 6 x 3072
#define SMEM_TOTAL (BL_OFF + 6 * 3072) // 94592

// ---------------------------------------------------------------------------
// Main (round-9 body + split commit groups): CTA = (batch, py, 16x8 input
// tile) -> both px parities, 256 output pixels x 64 oc. Group 0 = A+U+B[0..1]
// (waited before tap 0); group 1 = B[2..] (waited at tap 2). MMAs start after
// ~56KB of fill instead of 95KB.
// ---------------------------------------------------------------------------
__global__ __launch_bounds__(256, 2)
void tconv_mma(const float* __restrict__ mask,
               const float* __restrict__ high_b,
               float* __restrict__ out)
{
    extern __shared__ char smem[];
    const uint32_t sb = smem_u32(smem);
    const int tid = threadIdx.x;
    const int lane = tid & 31;
    const int warp = tid >> 5;
    const int wm = warp & 3;          // 4 warps along M
    const int wn = warp >> 2;         // 2 warps: oc halves [0,32) / [32,64)
    const int b = blockIdx.z, py = blockIdx.y;
    const int nty = py ? 2 : 1;
    const int T = 3 * nty;            // px0 taps then px1 taps
    const int x0 = (blockIdx.x & 15) * 16;
    const int y0 = (blockIdx.x >> 4) * 8;

    // ---- prologue group 0: A halo + U halo + B[0..1] ----
    {
        const size_t pix0 = (size_t)b * XP2 + (size_t)y0 * XP + x0;
        const __half* xbase = g_xh + pix0 * 64;
        #pragma unroll
        for (int i = 0; i < 5; ++i) {
            const int e = i * 256 + tid;
            if (e < HALO_ROWS * 8) {
                const int hr = e >> 3, c16 = (e & 7) << 4;
                const int ry = hr / 17, rx = hr - ry * 17;
                const char* src = (const char*)(xbase + ((size_t)ry * XP + rx) * 64) + c16;
                CP16(sb + A_OFF + (uint32_t)hr * 128 + (c16 ^ ((hr & 7) << 4)), src);
            }
        }
        const __half* ubase = g_u + pix0 * 16;
        #pragma unroll
        for (int i = 0; i < 2; ++i) {
            const int e = i * 256 + tid;
            if (e < HALO_ROWS * 2) {
                const int hr = e >> 1, c16 = (e & 1) << 4;
                const int ry = hr / 17, rx = hr - ry * 17;
                const char* src = (const char*)(ubase + ((size_t)ry * XP + rx) * 16) + c16;
                CP16(sb + U_OFF + (uint32_t)hr * 48 + c16, src);
            }
        }
        #pragma unroll
        for (int t = 0; t < 2; ++t) {
            const char* srcBH = (const char*)&g_BpH[py][t][0];
            CP16(sb + BH_OFF + t * 8192 + tid * 16, srcBH + tid * 16);
            CP16(sb + BH_OFF + t * 8192 + (256 + tid) * 16, srcBH + (256 + tid) * 16);
            if (tid < 192)
                CP16(sb + BL_OFF + t * 3072 + tid * 16,
                     (const char*)&g_BpL[py][t][0] + tid * 16);
        }
        CP_COMMIT();
        // ---- prologue group 1: B[2..T) ----
        #pragma unroll 1
        for (int t = 2; t < T; ++t) {
            const char* srcBH = (const char*)&g_BpH[py][t][0];
            CP16(sb + BH_OFF + t * 8192 + tid * 16, srcBH + tid * 16);
            CP16(sb + BH_OFF + t * 8192 + (256 + tid) * 16, srcBH + (256 + tid) * 16);
            if (tid < 192)
                CP16(sb + BL_OFF + t * 3072 + tid * 16,
                     (const char*)&g_BpL[py][t][0] + tid * 16);
        }
        CP_COMMIT();
        CP_WAIT1();                    // group 0 complete
        __syncthreads();
    }

    float accH[2][4][4], accL[2][4][4];
    #pragma unroll
    for (int i = 0; i < 2; ++i)
        #pragma unroll
        for (int j = 0; j < 4; ++j)
            #pragma unroll
            for (int k = 0; k < 4; ++k) { accH[i][j][k] = 0.f; accL[i][j][k] = 0.f; }

    // ---- masked direct-store epilogue (registers + gmem only) ----
    auto epi = [&](int px) {
        const int p = py * 2 + px;
        #pragma unroll
        for (int mf = 0; mf < 2; ++mf)
            #pragma unroll
            for (int rh = 0; rh < 2; ++rh) {
                const int m = wm * 32 + mf * 16 + (lane >> 2) + rh * 8;
                const int oy = 2 * (y0 + (m >> 4)) + py;
                const int ox = 2 * (x0 + (m & 15)) + px;
                const float mv = __ldg(mask + ((size_t)b * OHW + oy) * OHW + ox);
                const bool f = (mv >= 0.5f);
                float* obase = out + ((size_t)b * 64 * OHW + oy) * OHW + ox;
                #pragma unroll
                for (int j = 0; j < 4; ++j)
                    #pragma unroll
                    for (int rl = 0; rl < 2; ++rl) {
                        const int r = rh * 2 + rl;
                        const int oc = wn * 32 + j * 8 + (lane & 3) * 2 + rl;
                        const float v = f ? (accH[mf][j][r] + __ldg(high_b + oc))
                                          : (accL[mf][j][r] + g_biaslow[p][oc]);
                        obase[(size_t)oc * OHW * OHW] = v;
                    }
            }
    };

    #pragma unroll 1
    for (int t = 0; t < T; ++t) {
        if (t == 2) { CP_WAIT0(); __syncthreads(); }   // group 1 (B[2..]) ready

        int ty, tx;
        if (t < nty) { ty = t; tx = 0; }
        else { const int jj = t - nty; ty = jj >> 1; tx = jj & 1; }
        const uint32_t bbH = sb + BH_OFF + t * 8192;
        const uint32_t bbL = sb + BL_OFF + t * 3072;

        const int brow = (lane & 7) + ((lane >> 4) << 3);
        const int bkk  = ((lane >> 3) & 1) << 4;

        // ---- high GEMM: K=64 ----
        #pragma unroll
        for (int ks = 0; ks < 4; ++ks) {
            uint32_t ah[2][4];
            const int arow = lane & 15;
            const int akb = ks * 32 + ((lane >> 4) << 4);
            #pragma unroll
            for (int mf = 0; mf < 2; ++mf) {
                const int m = wm * 32 + mf * 16 + arow;
                const int hr = ((m >> 4) + ty) * 17 + (m & 15) + tx;
                ldsm4(ah[mf], sb + A_OFF + (uint32_t)hr * 128
                              + ((uint32_t)akb ^ ((uint32_t)(hr & 7) << 4)));
            }
            #pragma unroll
            for (int blk = 0; blk < 2; ++blk) {
                uint32_t bh[4];
                ldsm4(bh, bbH + swz128((uint32_t)(wn * 32 + blk * 16 + brow) * 128
                                       + ks * 32 + bkk));
                #pragma unroll
                for (int mf = 0; mf < 2; ++mf) {
                    mma16816(accH[mf][blk * 2 + 0], ah[mf], bh[0], bh[1]);
                    mma16816(accH[mf][blk * 2 + 1], ah[mf], bh[2], bh[3]);
                }
            }
        }

        // ---- low GEMM: K=16 over u ----
        {
            uint32_t au[2][4];
            const int arow = lane & 15;
            const int aku = (lane >> 4) << 4;
            #pragma unroll
            for (int mf = 0; mf < 2; ++mf) {
                const int m = wm * 32 + mf * 16 + arow;
                const int hr = ((m >> 4) + ty) * 17 + (m & 15) + tx;
                ldsm4(au[mf], sb + U_OFF + (uint32_t)hr * 48 + aku);
            }
            #pragma unroll
            for (int blk = 0; blk < 2; ++blk) {
                uint32_t bl[4];
                ldsm4(bl, bbL + (uint32_t)(wn * 32 + blk * 16 + brow) * 48 + bkk);
                #pragma unroll
                for (int mf = 0; mf < 2; ++mf) {
                    mma16816(accL[mf][blk * 2 + 0], au[mf], bl[0], bl[1]);
                    mma16816(accL[mf][blk * 2 + 1], au[mf], bl[2], bl[3]);
                }
            }
        }

        if (t == nty - 1) {             // px0 done: store + reset (no barrier)
            epi(0);
            #pragma unroll
            for (int i = 0; i < 2; ++i)
                #pragma unroll
                for (int j = 0; j < 4; ++j)
                    #pragma unroll
                    for (int k = 0; k < 4; ++k) { accH[i][j][k] = 0.f; accL[i][j][k] = 0.f; }
        }
    }

    epi(1);                             // px1 results
}

// ---------------------------------------------------------------------------
// Inputs: x, mask, inv_mask, high_w, high_b, low1_w, low1_b, low2_w, low2_b
// ---------------------------------------------------------------------------
extern "C" void kernel_launch(void* const* d_in, const int* in_sizes, int n_in,
                              void* d_out, int out_size)
{
    const float* x      = (const float*)d_in[0];
    const float* mask   = (const float*)d_in[1];
    const float* high_w = (const float*)d_in[3];
    const float* high_b = (const float*)d_in[4];
    const float* low1_w = (const float*)d_in[5];
    const float* low1_b = (const float*)d_in[6];
    const float* low2_w = (const float*)d_in[7];
    const float* low2_b = (const float*)d_in[8];
    float* out = (float*)d_out;

    cudaFuncSetAttribute(tconv_mma,
                         cudaFuncAttributeMaxDynamicSharedMemorySize, SMEM_TOTAL);

    prep_xu<<<dim3(XP, 5, 4), 256>>>(x, low1_w, high_w, low1_b, low2_w, low2_b);
    tconv_mma<<<dim3(512, 2, 4), 256, SMEM_TOTAL>>>(mask, high_b, out);
}

// round 16
// speedup vs baseline: 1.0147x; 1.0147x over previous
#include <cuda_runtime.h>
#include <cuda_fp16.h>
#include <cstdint>

#define HW   256
#define OHW  512
#define XP   257          // padded spatial dim (halo row/col of zeros)
#define XP2  (XP*XP)      // 66049
#define NPIX (4 * XP2)    // 264196 pixel rows

// ---------------------------------------------------------------------------
// g_xh: [b][y][x][c] fp16, 128B per (b,y,x), zero-padded at y/x==256 (+tail).
// g_u : [b][y][x][r] fp16 (r<16), u = x . low1^T, 32B per pixel.
// g_BpH: per (py, tapidx) 64(n) x 64(c) fp16 high weights, SW128 pre-swizzled.
// g_BpL: per (py, tapidx) 64(o) x 16(r) fp16 low2 weights, 24-half row pitch.
//   tapidx j: j<nty -> px=0 (ty=j,tx=0,kx=1); else jj=j-nty: px=1,
//   ty=jj>>1, tx=jj&1, kx = tx?0:2.  ky = py ? (ty?0:2) : 1.
// ---------------------------------------------------------------------------
__device__ __align__(16) __half g_xh[(NPIX + 256) * 64];
__device__ __align__(16) __half g_u [(NPIX + 256) * 16];
__device__ __align__(16) __half g_BpH[2][6][64 * 64];
__device__ __align__(16) __half g_BpL[2][6][64 * 24];
__device__ float g_biaslow[4][64];

static __device__ __forceinline__ uint32_t swz128(uint32_t off) {
    return off ^ ((off >> 3) & 0x70);
}
static __device__ __forceinline__ uint32_t smem_u32(const void* p) {
    uint32_t a;
    asm("{ .reg .u64 t; cvta.to.shared.u64 t, %1; cvt.u32.u64 %0, t; }" : "=r"(a) : "l"(p));
    return a;
}
static __device__ __forceinline__ void ldsm4(uint32_t r[4], uint32_t a) {
    asm volatile("ldmatrix.sync.aligned.m8n8.x4.shared.b16 {%0,%1,%2,%3}, [%4];"
        : "=r"(r[0]), "=r"(r[1]), "=r"(r[2]), "=r"(r[3]) : "r"(a));
}
static __device__ __forceinline__ void mma16816(float c[4], const uint32_t a[4],
                                                uint32_t b0, uint32_t b1) {
    asm volatile(
        "mma.sync.aligned.m16n8k16.row.col.f32.f16.f16.f32 "
        "{%0,%1,%2,%3}, {%4,%5,%6,%7}, {%8,%9}, {%0,%1,%2,%3};"
        : "+f"(c[0]), "+f"(c[1]), "+f"(c[2]), "+f"(c[3])
        : "r"(a[0]), "r"(a[1]), "r"(a[2]), "r"(a[3]), "r"(b0), "r"(b1));
}
#define CP16(dst, src) \
    asm volatile("cp.async.cg.shared.global [%0], [%1], 16;" :: "r"(dst), "l"(src))
#define CP_COMMIT() asm volatile("cp.async.commit_group;" ::: "memory")
#define CP_WAIT0()  asm volatile("cp.async.wait_group 0;" ::: "memory")

// ---------------------------------------------------------------------------
// Prep (fully fused, round-15 cp.async version): transpose x -> [b][y][x][c]
// fp16, u = x . low1^T -> g_u, weight packing on the 12 nearly-empty blocks
// (b==0, xc==256, y<12). Stage 1 cp.asyncs into an xor-chunked fp32 tile
// (chunk q of row c lands at q ^ (c>>3)) -> stage-2 gathers conflict-free.
// ---------------------------------------------------------------------------
__global__ void prep_xu(const float* __restrict__ x,
                        const float* __restrict__ low1_w,
                        const float* __restrict__ high_w,
                        const float* __restrict__ low1_b,
                        const float* __restrict__ low2_w,
                        const float* __restrict__ low2_b)
{
    __shared__ __align__(16) float tile[64 * 64];   // xor-chunk swizzled
    __shared__ __align__(16) char axs[8192];        // 64 rows x 128B, row-xor
    __shared__ __align__(16) char w1s[2048];        // 16 rows x 128B, SW128
    const int y  = blockIdx.x;            // 0..256
    const int xc = blockIdx.y * 64;       // 0,64,128,192,256
    const int b  = blockIdx.z;
    const int tid = threadIdx.x;
    const int lane = tid & 31;
    const int w = tid >> 5;
    const uint32_t st = smem_u32(tile);

    // ---- fused weight packing on 12 otherwise-idle blocks ----
    if (b == 0 && blockIdx.y == 4 && y < 12) {
        const int py = y / 6, j = y % 6;
        const int nty = py ? 2 : 1;
        const int T = 3 * nty;
        if (j < T) {
            int px, ty, tx;
            if (j < nty) { px = 0; ty = j; tx = 0; }
            else { const int jj = j - nty; px = 1; ty = jj >> 1; tx = jj & 1; }
            const int ky = py ? (ty ? 0 : 2) : 1;
            const int kx = px ? (tx ? 0 : 2) : 1;
            for (int idx = tid; idx < 64 * 64; idx += 256) {
                const int n = idx >> 6, c = idx & 63;
                g_BpH[py][j][swz128((uint32_t)n * 128 + c * 2) >> 1] =
                    __float2half(high_w[((c * 64 + n) * 3 + ky) * 3 + kx]);
            }
            for (int idx = tid; idx < 64 * 16; idx += 256) {
                const int o = idx >> 4, r = idx & 15;
                g_BpL[py][j][o * 24 + r] =
                    __float2half(low2_w[((r * 64 + o) * 3 + ky) * 3 + kx]);
            }
        }
        if (j == 0 && tid < 128) {
            const int px = tid >> 6, o = tid & 63;
            const int ntx = px ? 2 : 1;
            float s = low2_b[o];
            for (int ty = 0; ty < nty; ++ty)
                for (int tx = 0; tx < ntx; ++tx) {
                    const int ky = py ? (ty ? 0 : 2) : 1;
                    const int kx = px ? (tx ? 0 : 2) : 1;
                    for (int r = 0; r < 16; ++r)
                        s += low1_b[r] * low2_w[((r * 64 + o) * 3 + ky) * 3 + kx];
                }
            g_biaslow[py * 2 + px][o] = s;
        }
    }

    if (tid < 128) {
        const float* src = low1_w + (tid >> 3) * 64 + (tid & 7) * 8;
        __half h[8];
        #pragma unroll
        for (int k = 0; k < 8; ++k) h[k] = __float2half(src[k]);
        const uint32_t off = (uint32_t)(tid >> 3) * 128 + (tid & 7) * 16;
        *(uint4*)(w1s + (off ^ (((tid >> 3) & 7) << 4))) = *(const uint4*)h;
    }

    // ---- stage 1: fp32 tile fill (cp.async, xor-chunk layout) ----
    if (y < HW && xc < HW) {
        #pragma unroll
        for (int it = 0; it < 4; ++it) {
            const int e = it * 256 + tid;      // 1024 16B chunks
            const int c = e >> 4, q = e & 15;
            const char* src = (const char*)(x + (((size_t)b * 64 + c) * HW + y) * HW + xc)
                              + q * 16;
            CP16(st + (uint32_t)c * 256 + ((uint32_t)(q ^ (c >> 3)) << 4), src);
        }
        CP_COMMIT();
        CP_WAIT0();
    } else {
        #pragma unroll
        for (int it = 0; it < 16; ++it) tile[it * 256 + tid] = 0.f;
    }
    __syncthreads();

    // ---- stage 2: fp16 convert -> axs (for GEMM) + g_xh global ----
    #pragma unroll
    for (int it = 0; it < 2; ++it) {
        const int i = it * 256 + tid;          // 512 uint4 tasks
        const int xl = i >> 3, g = i & 7, ch = g << 3;
        const int xx = xc + xl;
        const float* trow = tile + ch * 64 + (((xl >> 2) ^ g) << 2) + (xl & 3);
        __half h[8];
        #pragma unroll
        for (int k = 0; k < 8; ++k) h[k] = __float2half(trow[k * 64]);
        const uint4 val = *(const uint4*)h;
        const uint32_t aoff = (uint32_t)xl * 128 + g * 16;
        *(uint4*)(axs + (aoff ^ (((uint32_t)(xl & 7)) << 4))) = val;
        if (xx <= 256)
            *(uint4*)&g_xh[((size_t)b * XP2 + (size_t)y * XP + xx) * 64 + ch] = val;
    }
    __syncthreads();

    // ---- stage 3: u = X . W1^T (warps 0-1) ----
    if (w < 2) {
        const uint32_t sa = smem_u32(axs), sw = smem_u32(w1s);
        float acc[2][2][4];
        #pragma unroll
        for (int i = 0; i < 2; ++i)
            #pragma unroll
            for (int j = 0; j < 2; ++j)
                #pragma unroll
                for (int k = 0; k < 4; ++k) acc[i][j][k] = 0.f;

        const int brow = (lane & 7) + ((lane >> 4) << 3);
        const int bkk  = ((lane >> 3) & 1) << 4;
        #pragma unroll
        for (int ks = 0; ks < 4; ++ks) {
            uint32_t a[2][4];
            const int arow = lane & 15;
            const int akb = ks * 32 + ((lane >> 4) << 4);
            #pragma unroll
            for (int mf = 0; mf < 2; ++mf) {
                const int row = w * 32 + mf * 16 + arow;
                ldsm4(a[mf], sa + (uint32_t)row * 128
                              + ((uint32_t)akb ^ ((uint32_t)(row & 7) << 4)));
            }
            uint32_t bw[4];
            ldsm4(bw, sw + swz128((uint32_t)brow * 128 + ks * 32 + bkk));
            #pragma unroll
            for (int mf = 0; mf < 2; ++mf) {
                mma16816(acc[mf][0], a[mf], bw[0], bw[1]);
                mma16816(acc[mf][1], a[mf], bw[2], bw[3]);
            }
        }
        #pragma unroll
        for (int mf = 0; mf < 2; ++mf)
            #pragma unroll
            for (int j = 0; j < 2; ++j)
                #pragma unroll
                for (int rh = 0; rh < 2; ++rh) {
                    const int row = w * 32 + mf * 16 + (lane >> 2) + rh * 8;
                    const int xx = xc + row;
                    if (xx <= 256) {
                        const int col = j * 8 + (lane & 3) * 2;
                        __half2 hv = __floats2half2_rn(acc[mf][j][rh * 2],
                                                       acc[mf][j][rh * 2 + 1]);
                        *(__half2*)&g_u[((size_t)b * XP2 + (size_t)y * XP + xx) * 16
                                        + col] = hv;
                    }
                }
    }
}

// SMEM map (main kernel) — everything resident, read-only after one sync.
#define A_OFF      0
#define HALO_ROWS  153                 // 9 x 17
#define U_OFF      19584               // 153 x 48B
#define BH_OFF     27008               // 6 x 8192
#define BL_OFF     (BH_OFF + 6 * 8192) // 76160; 6 x 3072
#define SMEM_TOTAL (BL_OFF + 6 * 3072) // 94592

// ---------------------------------------------------------------------------
// Main (round-14 body, verbatim — best measured 169.2-170.6us): CTA =
// (batch, py, 16x8 input tile) -> both px parities, 256 output pixels x 64
// oc. Single commit group, one wait, ONE barrier; barrier-free tap loop;
// direct masked stride-2 stores.
// ---------------------------------------------------------------------------
__global__ __launch_bounds__(256, 2)
void tconv_mma(const float* __restrict__ mask,
               const float* __restrict__ high_b,
               float* __restrict__ out)
{
    extern __shared__ char smem[];
    const uint32_t sb = smem_u32(smem);
    const int tid = threadIdx.x;
    const int lane = tid & 31;
    const int warp = tid >> 5;
    const int wm = warp & 3;          // 4 warps along M
    const int wn = warp >> 2;         // 2 warps: oc halves [0,32) / [32,64)
    const int b = blockIdx.z, py = blockIdx.y;
    const int nty = py ? 2 : 1;
    const int T = 3 * nty;            // px0 taps then px1 taps
    const int x0 = (blockIdx.x & 15) * 16;
    const int y0 = (blockIdx.x >> 4) * 8;

    // ---- prologue: A halo + U halo + ALL B tiles; one wait, one sync ----
    {
        const size_t pix0 = (size_t)b * XP2 + (size_t)y0 * XP + x0;
        const __half* xbase = g_xh + pix0 * 64;
        #pragma unroll
        for (int i = 0; i < 5; ++i) {
            const int e = i * 256 + tid;
            if (e < HALO_ROWS * 8) {
                const int hr = e >> 3, c16 = (e & 7) << 4;
                const int ry = hr / 17, rx = hr - ry * 17;
                const char* src = (const char*)(xbase + ((size_t)ry * XP + rx) * 64) + c16;
                CP16(sb + A_OFF + (uint32_t)hr * 128 + (c16 ^ ((hr & 7) << 4)), src);
            }
        }
        const __half* ubase = g_u + pix0 * 16;
        #pragma unroll
        for (int i = 0; i < 2; ++i) {
            const int e = i * 256 + tid;
            if (e < HALO_ROWS * 2) {
                const int hr = e >> 1, c16 = (e & 1) << 4;
                const int ry = hr / 17, rx = hr - ry * 17;
                const char* src = (const char*)(ubase + ((size_t)ry * XP + rx) * 16) + c16;
                CP16(sb + U_OFF + (uint32_t)hr * 48 + c16, src);
            }
        }
        #pragma unroll 1
        for (int t = 0; t < T; ++t) {
            const char* srcBH = (const char*)&g_BpH[py][t][0];
            CP16(sb + BH_OFF + t * 8192 + tid * 16, srcBH + tid * 16);
            CP16(sb + BH_OFF + t * 8192 + (256 + tid) * 16, srcBH + (256 + tid) * 16);
            if (tid < 192)
                CP16(sb + BL_OFF + t * 3072 + tid * 16,
                     (const char*)&g_BpL[py][t][0] + tid * 16);
        }
        CP_COMMIT();
        CP_WAIT0();
        __syncthreads();               // the ONLY barrier in this kernel
    }

    float accH[2][4][4], accL[2][4][4];
    #pragma unroll
    for (int i = 0; i < 2; ++i)
        #pragma unroll
        for (int j = 0; j < 4; ++j)
            #pragma unroll
            for (int k = 0; k < 4; ++k) { accH[i][j][k] = 0.f; accL[i][j][k] = 0.f; }

    // ---- masked direct-store epilogue (registers + gmem only) ----
    auto epi = [&](int px) {
        const int p = py * 2 + px;
        #pragma unroll
        for (int mf = 0; mf < 2; ++mf)
            #pragma unroll
            for (int rh = 0; rh < 2; ++rh) {
                const int m = wm * 32 + mf * 16 + (lane >> 2) + rh * 8;
                const int oy = 2 * (y0 + (m >> 4)) + py;
                const int ox = 2 * (x0 + (m & 15)) + px;
                const float mv = __ldg(mask + ((size_t)b * OHW + oy) * OHW + ox);
                const bool f = (mv >= 0.5f);
                float* obase = out + ((size_t)b * 64 * OHW + oy) * OHW + ox;
                #pragma unroll
                for (int j = 0; j < 4; ++j)
                    #pragma unroll
                    for (int rl = 0; rl < 2; ++rl) {
                        const int r = rh * 2 + rl;
                        const int oc = wn * 32 + j * 8 + (lane & 3) * 2 + rl;
                        const float v = f ? (accH[mf][j][r] + __ldg(high_b + oc))
                                          : (accL[mf][j][r] + g_biaslow[p][oc]);
                        obase[(size_t)oc * OHW * OHW] = v;
                    }
            }
    };

    #pragma unroll 1
    for (int t = 0; t < T; ++t) {
        int ty, tx;
        if (t < nty) { ty = t; tx = 0; }
        else { const int jj = t - nty; ty = jj >> 1; tx = jj & 1; }
        const uint32_t bbH = sb + BH_OFF + t * 8192;
        const uint32_t bbL = sb + BL_OFF + t * 3072;

        const int brow = (lane & 7) + ((lane >> 4) << 3);
        const int bkk  = ((lane >> 3) & 1) << 4;

        // ---- high GEMM: K=64 ----
        #pragma unroll
        for (int ks = 0; ks < 4; ++ks) {
            uint32_t ah[2][4];
            const int arow = lane & 15;
            const int akb = ks * 32 + ((lane >> 4) << 4);
            #pragma unroll
            for (int mf = 0; mf < 2; ++mf) {
                const int m = wm * 32 + mf * 16 + arow;
                const int hr = ((m >> 4) + ty) * 17 + (m & 15) + tx;
                ldsm4(ah[mf], sb + A_OFF + (uint32_t)hr * 128
                              + ((uint32_t)akb ^ ((uint32_t)(hr & 7) << 4)));
            }
            #pragma unroll
            for (int blk = 0; blk < 2; ++blk) {
                uint32_t bh[4];
                ldsm4(bh, bbH + swz128((uint32_t)(wn * 32 + blk * 16 + brow) * 128
                                       + ks * 32 + bkk));
                #pragma unroll
                for (int mf = 0; mf < 2; ++mf) {
                    mma16816(accH[mf][blk * 2 + 0], ah[mf], bh[0], bh[1]);
                    mma16816(accH[mf][blk * 2 + 1], ah[mf], bh[2], bh[3]);
                }
            }
        }

        // ---- low GEMM: K=16 over u ----
        {
            uint32_t au[2][4];
            const int arow = lane & 15;
            const int aku = (lane >> 4) << 4;
            #pragma unroll
            for (int mf = 0; mf < 2; ++mf) {
                const int m = wm * 32 + mf * 16 + arow;
                const int hr = ((m >> 4) + ty) * 17 + (m & 15) + tx;
                ldsm4(au[mf], sb + U_OFF + (uint32_t)hr * 48 + aku);
            }
            #pragma unroll
            for (int blk = 0; blk < 2; ++blk) {
                uint32_t bl[4];
                ldsm4(bl, bbL + (uint32_t)(wn * 32 + blk * 16 + brow) * 48 + bkk);
                #pragma unroll
                for (int mf = 0; mf < 2; ++mf) {
                    mma16816(accL[mf][blk * 2 + 0], au[mf], bl[0], bl[1]);
                    mma16816(accL[mf][blk * 2 + 1], au[mf], bl[2], bl[3]);
                }
            }
        }

        if (t == nty - 1) {             // px0 done: store + reset (no barrier)
            epi(0);
            #pragma unroll
            for (int i = 0; i < 2; ++i)
                #pragma unroll
                for (int j = 0; j < 4; ++j)
                    #pragma unroll
                    for (int k = 0; k < 4; ++k) { accH[i][j][k] = 0.f; accL[i][j][k] = 0.f; }
        }
    }

    epi(1);                             // px1 results
}

// ---------------------------------------------------------------------------
// Inputs: x, mask, inv_mask, high_w, high_b, low1_w, low1_b, low2_w, low2_b
// ---------------------------------------------------------------------------
extern "C" void kernel_launch(void* const* d_in, const int* in_sizes, int n_in,
                              void* d_out, int out_size)
{
    const float* x      = (const float*)d_in[0];
    const float* mask   = (const float*)d_in[1];
    const float* high_w = (const float*)d_in[3];
    const float* high_b = (const float*)d_in[4];
    const float* low1_w = (const float*)d_in[5];
    const float* low1_b = (const float*)d_in[6];
    const float* low2_w = (const float*)d_in[7];
    const float* low2_b = (const float*)d_in[8];
    float* out = (float*)d_out;

    cudaFuncSetAttribute(tconv_mma,
                         cudaFuncAttributeMaxDynamicSharedMemorySize, SMEM_TOTAL);

    prep_xu<<<dim3(XP, 5, 4), 256>>>(x, low1_w, high_w, low1_b, low2_w, low2_b);
    tconv_mma<<<dim3(512, 2, 4), 256, SMEM_TOTAL>>>(mask, high_b, out);
}